// round 2
// baseline (speedup 1.0000x reference)
#include <cuda_runtime.h>
#include <cuda_bf16.h>
#include <cstdint>

#define SEQ   2048
#define BATCH 64
#define DIM   512
#define HID   512
#define GATE  2048   // 4*HID
#define NBLK  64

// ---------------- device scratch (static globals are allowed) ---------------
__device__ float g_xg[(size_t)SEQ * BATCH * GATE];   // precomputed input gates [S*B][4H]
__device__ float g_h[2][BATCH * HID];                // double-buffered hidden state
__device__ unsigned g_bar_count = 0;
__device__ volatile unsigned g_bar_gen = 0;

// ---------------- helpers ----------------------------------------------------
__device__ __forceinline__ float tf32r(float f) {
    uint32_t u;
    asm("cvt.rna.tf32.f32 %0, %1;" : "=r"(u) : "f"(f));
    return __uint_as_float(u);
}
__device__ __forceinline__ uint32_t f2tf32(float f) {
    uint32_t u;
    asm("cvt.rna.tf32.f32 %0, %1;" : "=r"(u) : "f"(f));
    return u;
}
__device__ __forceinline__ void mma_tf32(float* c, const uint32_t* a, const uint32_t* b) {
    asm volatile(
        "mma.sync.aligned.m16n8k8.row.col.f32.tf32.tf32.f32 "
        "{%0,%1,%2,%3}, {%4,%5,%6,%7}, {%8,%9}, {%0,%1,%2,%3};"
        : "+f"(c[0]), "+f"(c[1]), "+f"(c[2]), "+f"(c[3])
        : "r"(a[0]), "r"(a[1]), "r"(a[2]), "r"(a[3]), "r"(b[0]), "r"(b[1]));
}
__device__ __forceinline__ float sigf(float x) { return 1.0f / (1.0f + __expf(-x)); }
__device__ __forceinline__ float tanhfast(float x) { return 2.0f / (1.0f + __expf(-2.0f * x)) - 1.0f; }

// =============================================================================
// Phase 1: Xg[m, n] = x[m, :] . W_ih[n, :] + b_ih[n] + b_hh[n]
// M = 131072, N = 2048, K = 512. Block 128x128 (256 thr), warp 64x32.
// =============================================================================
__global__ __launch_bounds__(256) void lstm_xgemm(
    const float* __restrict__ x, const float* __restrict__ Wih,
    const float* __restrict__ bih, const float* __restrict__ bhh)
{
    __shared__ float As[128 * 36];
    __shared__ float Bs[128 * 36];
    __shared__ float bsum[128];

    const int t = threadIdx.x;
    const int warp = t >> 5, lane = t & 31;
    const int wm = warp & 1;    // m warp offset (0/1) * 64
    const int wn = warp >> 1;   // n warp offset (0..3) * 32
    const int g = lane >> 2, tig = lane & 3;
    const int m0 = blockIdx.y * 128;
    const int n0 = blockIdx.x * 128;

    if (t < 128) bsum[t] = bih[n0 + t] + bhh[n0 + t];

    float acc[4][4][4];
#pragma unroll
    for (int mt = 0; mt < 4; mt++)
#pragma unroll
        for (int nt = 0; nt < 4; nt++)
#pragma unroll
            for (int i = 0; i < 4; i++) acc[mt][nt][i] = 0.f;

    for (int kc = 0; kc < 512; kc += 32) {
        __syncthreads();
#pragma unroll
        for (int i = 0; i < 4; i++) {
            int f = t + i * 256;
            int row = f >> 3, q = (f & 7) * 4;
            float4 v = *reinterpret_cast<const float4*>(x + (size_t)(m0 + row) * 512 + kc + q);
            float* d = As + row * 36 + q;
            d[0] = tf32r(v.x); d[1] = tf32r(v.y); d[2] = tf32r(v.z); d[3] = tf32r(v.w);
        }
#pragma unroll
        for (int i = 0; i < 4; i++) {
            int f = t + i * 256;
            int row = f >> 3, q = (f & 7) * 4;
            float4 v = *reinterpret_cast<const float4*>(Wih + (size_t)(n0 + row) * 512 + kc + q);
            float* d = Bs + row * 36 + q;
            d[0] = tf32r(v.x); d[1] = tf32r(v.y); d[2] = tf32r(v.z); d[3] = tf32r(v.w);
        }
        __syncthreads();

#pragma unroll
        for (int kt = 0; kt < 4; kt++) {
            const int k = kt * 8;
            uint32_t a[4][4], b[4][2];
#pragma unroll
            for (int mt = 0; mt < 4; mt++) {
                const int r = wm * 64 + mt * 16;
                a[mt][0] = __float_as_uint(As[(r + g) * 36 + k + tig]);
                a[mt][1] = __float_as_uint(As[(r + g + 8) * 36 + k + tig]);
                a[mt][2] = __float_as_uint(As[(r + g) * 36 + k + tig + 4]);
                a[mt][3] = __float_as_uint(As[(r + g + 8) * 36 + k + tig + 4]);
            }
#pragma unroll
            for (int nt = 0; nt < 4; nt++) {
                const int rn = wn * 32 + nt * 8;
                b[nt][0] = __float_as_uint(Bs[(rn + g) * 36 + k + tig]);
                b[nt][1] = __float_as_uint(Bs[(rn + g) * 36 + k + tig + 4]);
            }
#pragma unroll
            for (int mt = 0; mt < 4; mt++)
#pragma unroll
                for (int nt = 0; nt < 4; nt++)
                    mma_tf32(acc[mt][nt], a[mt], b[nt]);
        }
    }

#pragma unroll
    for (int mt = 0; mt < 4; mt++) {
        const int r0 = m0 + wm * 64 + mt * 16 + g;
#pragma unroll
        for (int nt = 0; nt < 4; nt++) {
            const int cl = wn * 32 + nt * 8 + 2 * tig;
            const float b0 = bsum[cl], b1 = bsum[cl + 1];
            float2 v0 = make_float2(acc[mt][nt][0] + b0, acc[mt][nt][1] + b1);
            float2 v1 = make_float2(acc[mt][nt][2] + b0, acc[mt][nt][3] + b1);
            *reinterpret_cast<float2*>(g_xg + (size_t)r0 * GATE + n0 + cl)       = v0;
            *reinterpret_cast<float2*>(g_xg + (size_t)(r0 + 8) * GATE + n0 + cl) = v1;
        }
    }
}

// =============================================================================
// Phase 2: persistent recurrence. 64 CTAs = 2 batch-groups x 32 col-groups.
// =============================================================================
__device__ __forceinline__ void grid_barrier() {
    __threadfence();
    __syncthreads();
    if (threadIdx.x == 0) {
        unsigned gv = g_bar_gen;
        if (atomicAdd(&g_bar_count, 1u) == NBLK - 1u) {
            g_bar_count = 0u;
            __threadfence();
            g_bar_gen = gv + 1u;
        } else {
            while (g_bar_gen == gv) { }
        }
        __threadfence();
    }
    __syncthreads();
}

__global__ __launch_bounds__(256) void lstm_rec(const float* __restrict__ Whh,
                                                float* __restrict__ out)
{
    extern __shared__ float part[];   // [8 warps][64 rows][34] floats = 69632 B
    const int t = threadIdx.x, warp = t >> 5, lane = t & 31;
    const int g = lane >> 2, tig = lane & 3;
    const int bg = blockIdx.x & 1;
    const int cg = blockIdx.x >> 1;
    const int nb0 = bg * 32;          // batch base
    const int hc0 = cg * 16;          // h-column base
    const int ks = warp * 64;         // this warp's k-slice

    // ---- resident W_hh fragments (tf32), 128 regs/thread ----
    uint32_t wfr[4][8][4];
#pragma unroll
    for (int mt = 0; mt < 4; mt++) {
        const float* w0 = Whh + (size_t)(mt * 512 + hc0 + g) * 512;
        const float* w8 = Whh + (size_t)(mt * 512 + hc0 + g + 8) * 512;
#pragma unroll
        for (int kt = 0; kt < 8; kt++) {
            const int k = ks + kt * 8 + tig;
            wfr[mt][kt][0] = f2tf32(w0[k]);
            wfr[mt][kt][1] = f2tf32(w8[k]);
            wfr[mt][kt][2] = f2tf32(w0[k + 4]);
            wfr[mt][kt][3] = f2tf32(w8[k + 4]);
        }
    }

    // output mapping: this thread owns (h-cols gc, gc+1) x batch gb
    const int r  = 2 * (t & 7);       // local col pair base, 0..14
    const int cb = t >> 3;            // local batch, 0..31
    const int gb = nb0 + cb;
    const int gc = hc0 + r;

    // init h0 = 0, c0 = 0
    *reinterpret_cast<float2*>(&g_h[0][gb * HID + gc]) = make_float2(0.f, 0.f);
    float c0 = 0.f, c1 = 0.f, hv0 = 0.f, hv1 = 0.f;
    grid_barrier();

    int p = 0;
    for (int s = 0; s < SEQ; s++) {
        // prefetch Xg early (DRAM latency hidden behind mma + reduce)
        const float* xr = g_xg + ((size_t)s * BATCH + gb) * GATE + gc;
        const float2 xi = *reinterpret_cast<const float2*>(xr + 0 * 512);
        const float2 xf = *reinterpret_cast<const float2*>(xr + 1 * 512);
        const float2 xg = *reinterpret_cast<const float2*>(xr + 2 * 512);
        const float2 xo = *reinterpret_cast<const float2*>(xr + 3 * 512);

        const float* hsrc = g_h[p];
        float acc[4][4][4];
#pragma unroll
        for (int mt = 0; mt < 4; mt++)
#pragma unroll
            for (int nt = 0; nt < 4; nt++)
#pragma unroll
                for (int i = 0; i < 4; i++) acc[mt][nt][i] = 0.f;

        // ---- h @ W_hh^T partial over this warp's k slice ----
        uint32_t bb[2][4][2];
#pragma unroll
        for (int nt = 0; nt < 4; nt++) {
            const float* hp = hsrc + (size_t)(nb0 + nt * 8 + g) * HID + ks + tig;
            bb[0][nt][0] = f2tf32(hp[0]);
            bb[0][nt][1] = f2tf32(hp[4]);
        }
#pragma unroll
        for (int kt = 0; kt < 8; kt++) {
            const int cur = kt & 1;
            if (kt < 7) {
#pragma unroll
                for (int nt = 0; nt < 4; nt++) {
                    const float* hp = hsrc + (size_t)(nb0 + nt * 8 + g) * HID + ks + (kt + 1) * 8 + tig;
                    bb[cur ^ 1][nt][0] = f2tf32(hp[0]);
                    bb[cur ^ 1][nt][1] = f2tf32(hp[4]);
                }
            }
#pragma unroll
            for (int mt = 0; mt < 4; mt++)
#pragma unroll
                for (int nt = 0; nt < 4; nt++)
                    mma_tf32(acc[mt][nt], wfr[mt][kt], bb[cur][nt]);
        }

        // ---- store k-partials to smem ----
        float* pw = part + warp * (64 * 34);
#pragma unroll
        for (int mt = 0; mt < 4; mt++)
#pragma unroll
            for (int nt = 0; nt < 4; nt++) {
                const int row = mt * 16 + g, col = nt * 8 + 2 * tig;
                *reinterpret_cast<float2*>(pw + row * 34 + col) =
                    make_float2(acc[mt][nt][0], acc[mt][nt][1]);
                *reinterpret_cast<float2*>(pw + (row + 8) * 34 + col) =
                    make_float2(acc[mt][nt][2], acc[mt][nt][3]);
            }
        __syncthreads();

        // ---- reduce 8 partials + activations + state update ----
        float sg[4][2];
#pragma unroll
        for (int gt = 0; gt < 4; gt++)
#pragma unroll
            for (int j = 0; j < 2; j++) {
                const int base = (gt * 16 + r + j) * 34 + cb;
                float v = part[base];
#pragma unroll
                for (int w = 1; w < 8; w++) v += part[w * (64 * 34) + base];
                sg[gt][j] = v;
            }

        const float i0 = sigf(xi.x + sg[0][0]);
        const float i1 = sigf(xi.y + sg[0][1]);
        const float f0 = sigf(xf.x + sg[1][0]);
        const float f1 = sigf(xf.y + sg[1][1]);
        const float g0 = tanhfast(xg.x + sg[2][0]);
        const float g1 = tanhfast(xg.y + sg[2][1]);
        const float o0 = sigf(xo.x + sg[3][0]);
        const float o1 = sigf(xo.y + sg[3][1]);

        c0 = f0 * c0 + i0 * g0;
        c1 = f1 * c1 + i1 * g1;
        hv0 = o0 * tanhfast(c0);
        hv1 = o1 * tanhfast(c1);

        const float2 hvv = make_float2(hv0, hv1);
        *reinterpret_cast<float2*>(&g_h[p ^ 1][gb * HID + gc]) = hvv;
        *reinterpret_cast<float2*>(out + ((size_t)s * BATCH + gb) * HID + gc) = hvv;

        grid_barrier();
        p ^= 1;
    }

    // final h, c
    float* hf = out + (size_t)SEQ * BATCH * HID;
    float* cf = hf + (size_t)BATCH * HID;
    *reinterpret_cast<float2*>(hf + gb * HID + gc) = make_float2(hv0, hv1);
    *reinterpret_cast<float2*>(cf + gb * HID + gc) = make_float2(c0, c1);
}

// =============================================================================
extern "C" void kernel_launch(void* const* d_in, const int* in_sizes, int n_in,
                              void* d_out, int out_size) {
    const float* x   = (const float*)d_in[0];
    const float* Wih = (const float*)d_in[1];
    const float* Whh = (const float*)d_in[2];
    const float* bih = (const float*)d_in[3];
    const float* bhh = (const float*)d_in[4];
    float* out = (float*)d_out;

    dim3 grid1(16, 1024);
    lstm_xgemm<<<grid1, 256>>>(x, Wih, bih, bhh);

    const int smem2 = 8 * 64 * 34 * (int)sizeof(float);  // 69632
    cudaFuncSetAttribute(lstm_rec, cudaFuncAttributeMaxDynamicSharedMemorySize, smem2);
    lstm_rec<<<NBLK, 256, smem2>>>(Whh, out);
}

// round 4
// speedup vs baseline: 1.0092x; 1.0092x over previous
#include <cuda_runtime.h>
#include <cuda_bf16.h>
#include <cstdint>

#define SEQ   2048
#define BATCH 64
#define DIM   512
#define HID   512
#define GATE  2048   // 4*HID
#define NBLK  64

// ---------------- device scratch (static globals are allowed) ---------------
__device__ float g_xg[(size_t)SEQ * BATCH * GATE];   // precomputed input gates [S*B][4H]
__device__ float g_h[2][BATCH * HID];                // double-buffered hidden state
__device__ unsigned g_bar_count = 0;
__device__ unsigned g_bar_gen = 0;

// ---------------- helpers ----------------------------------------------------
__device__ __forceinline__ float tf32r(float f) {
    uint32_t u;
    asm("cvt.rna.tf32.f32 %0, %1;" : "=r"(u) : "f"(f));
    return __uint_as_float(u);
}
__device__ __forceinline__ uint32_t f2tf32(float f) {
    uint32_t u;
    asm("cvt.rna.tf32.f32 %0, %1;" : "=r"(u) : "f"(f));
    return u;
}
__device__ __forceinline__ void mma_tf32(float* c, const uint32_t* a, const uint32_t* b) {
    asm volatile(
        "mma.sync.aligned.m16n8k8.row.col.f32.tf32.tf32.f32 "
        "{%0,%1,%2,%3}, {%4,%5,%6,%7}, {%8,%9}, {%0,%1,%2,%3};"
        : "+f"(c[0]), "+f"(c[1]), "+f"(c[2]), "+f"(c[3])
        : "r"(a[0]), "r"(a[1]), "r"(a[2]), "r"(a[3]), "r"(b[0]), "r"(b[1]));
}
__device__ __forceinline__ float sigf(float x) { return 1.0f / (1.0f + __expf(-x)); }
__device__ __forceinline__ float tanhfast(float x) { return 2.0f / (1.0f + __expf(-2.0f * x)) - 1.0f; }

// =============================================================================
// Phase 1: Xg[m, n] = x[m, :] . W_ih[n, :] + b_ih[n] + b_hh[n]
// M = 131072, N = 2048, K = 512. Block 128x128 (256 thr), warp 64x32.
// =============================================================================
__global__ __launch_bounds__(256) void lstm_xgemm(
    const float* __restrict__ x, const float* __restrict__ Wih,
    const float* __restrict__ bih, const float* __restrict__ bhh)
{
    __shared__ float As[128 * 36];
    __shared__ float Bs[128 * 36];
    __shared__ float bsum[128];

    const int t = threadIdx.x;
    const int warp = t >> 5, lane = t & 31;
    const int wm = warp & 1;
    const int wn = warp >> 1;
    const int g = lane >> 2, tig = lane & 3;
    const int m0 = blockIdx.y * 128;
    const int n0 = blockIdx.x * 128;

    if (t < 128) bsum[t] = bih[n0 + t] + bhh[n0 + t];

    float acc[4][4][4];
#pragma unroll
    for (int mt = 0; mt < 4; mt++)
#pragma unroll
        for (int nt = 0; nt < 4; nt++)
#pragma unroll
            for (int i = 0; i < 4; i++) acc[mt][nt][i] = 0.f;

    for (int kc = 0; kc < 512; kc += 32) {
        __syncthreads();
#pragma unroll
        for (int i = 0; i < 4; i++) {
            int f = t + i * 256;
            int row = f >> 3, q = (f & 7) * 4;
            float4 v = *reinterpret_cast<const float4*>(x + (size_t)(m0 + row) * 512 + kc + q);
            float* d = As + row * 36 + q;
            d[0] = tf32r(v.x); d[1] = tf32r(v.y); d[2] = tf32r(v.z); d[3] = tf32r(v.w);
        }
#pragma unroll
        for (int i = 0; i < 4; i++) {
            int f = t + i * 256;
            int row = f >> 3, q = (f & 7) * 4;
            float4 v = *reinterpret_cast<const float4*>(Wih + (size_t)(n0 + row) * 512 + kc + q);
            float* d = Bs + row * 36 + q;
            d[0] = tf32r(v.x); d[1] = tf32r(v.y); d[2] = tf32r(v.z); d[3] = tf32r(v.w);
        }
        __syncthreads();

#pragma unroll
        for (int kt = 0; kt < 4; kt++) {
            const int k = kt * 8;
            uint32_t a[4][4], b[4][2];
#pragma unroll
            for (int mt = 0; mt < 4; mt++) {
                const int r = wm * 64 + mt * 16;
                a[mt][0] = __float_as_uint(As[(r + g) * 36 + k + tig]);
                a[mt][1] = __float_as_uint(As[(r + g + 8) * 36 + k + tig]);
                a[mt][2] = __float_as_uint(As[(r + g) * 36 + k + tig + 4]);
                a[mt][3] = __float_as_uint(As[(r + g + 8) * 36 + k + tig + 4]);
            }
#pragma unroll
            for (int nt = 0; nt < 4; nt++) {
                const int rn = wn * 32 + nt * 8;
                b[nt][0] = __float_as_uint(Bs[(rn + g) * 36 + k + tig]);
                b[nt][1] = __float_as_uint(Bs[(rn + g) * 36 + k + tig + 4]);
            }
#pragma unroll
            for (int mt = 0; mt < 4; mt++)
#pragma unroll
                for (int nt = 0; nt < 4; nt++)
                    mma_tf32(acc[mt][nt], a[mt], b[nt]);
        }
    }

#pragma unroll
    for (int mt = 0; mt < 4; mt++) {
        const int r0 = m0 + wm * 64 + mt * 16 + g;
#pragma unroll
        for (int nt = 0; nt < 4; nt++) {
            const int cl = wn * 32 + nt * 8 + 2 * tig;
            const float b0 = bsum[cl], b1 = bsum[cl + 1];
            float2 v0 = make_float2(acc[mt][nt][0] + b0, acc[mt][nt][1] + b1);
            float2 v1 = make_float2(acc[mt][nt][2] + b0, acc[mt][nt][3] + b1);
            *reinterpret_cast<float2*>(g_xg + (size_t)r0 * GATE + n0 + cl)       = v0;
            *reinterpret_cast<float2*>(g_xg + (size_t)(r0 + 8) * GATE + n0 + cl) = v1;
        }
    }
}

// =============================================================================
// Phase 2: persistent recurrence. 64 CTAs = 2 batch-groups x 32 col-groups.
// Barrier: release-atomic arrive + acquire-load spin with nanosleep backoff
// (NO __threadfence -> no CCTL.IVALL L1 flush). h goes through L2 (__ldcg).
// =============================================================================
__device__ __forceinline__ void grid_barrier() {
    __syncthreads();
    if (threadIdx.x == 0) {
        unsigned* cnt = &g_bar_count;
        unsigned* gen = &g_bar_gen;
        unsigned gv;
        asm volatile("ld.acquire.gpu.global.u32 %0, [%1];" : "=r"(gv) : "l"(gen) : "memory");
        unsigned old;
        asm volatile("atom.release.gpu.global.add.u32 %0, [%1], %2;"
                     : "=r"(old) : "l"(cnt), "r"(1u) : "memory");
        if (old == NBLK - 1u) {
            asm volatile("st.relaxed.gpu.global.u32 [%0], %1;" :: "l"(cnt), "r"(0u) : "memory");
            asm volatile("st.release.gpu.global.u32 [%0], %1;" :: "l"(gen), "r"(gv + 1u) : "memory");
        } else {
            unsigned cur;
            while (true) {
                asm volatile("ld.acquire.gpu.global.u32 %0, [%1];" : "=r"(cur) : "l"(gen) : "memory");
                if (cur != gv) break;
                __nanosleep(200);
            }
        }
    }
    __syncthreads();
}

__global__ __launch_bounds__(256) void lstm_rec(const float* __restrict__ Whh,
                                                float* __restrict__ out)
{
    extern __shared__ float part[];   // [8 warps][64 rows][34] floats = 69632 B
    const int t = threadIdx.x, warp = t >> 5, lane = t & 31;
    const int g = lane >> 2, tig = lane & 3;
    const int bg = blockIdx.x & 1;
    const int cg = blockIdx.x >> 1;
    const int nb0 = bg * 32;          // batch base
    const int hc0 = cg * 16;          // h-column base
    const int ks = warp * 64;         // this warp's k-slice

    // ---- resident W_hh fragments (tf32), 128 regs/thread ----
    uint32_t wfr[4][8][4];
#pragma unroll
    for (int mt = 0; mt < 4; mt++) {
        const float* w0 = Whh + (size_t)(mt * 512 + hc0 + g) * 512;
        const float* w8 = Whh + (size_t)(mt * 512 + hc0 + g + 8) * 512;
#pragma unroll
        for (int kt = 0; kt < 8; kt++) {
            const int k = ks + kt * 8 + tig;
            wfr[mt][kt][0] = f2tf32(w0[k]);
            wfr[mt][kt][1] = f2tf32(w8[k]);
            wfr[mt][kt][2] = f2tf32(w0[k + 4]);
            wfr[mt][kt][3] = f2tf32(w8[k + 4]);
        }
    }

    // output mapping: this thread owns (h-cols gc, gc+1) x batch gb
    const int r  = 2 * (t & 7);       // local col pair base, 0..14
    const int cb = t >> 3;            // local batch, 0..31
    const int gb = nb0 + cb;
    const int gc = hc0 + r;

    // init h0 = 0, c0 = 0
    *reinterpret_cast<float2*>(&g_h[0][gb * HID + gc]) = make_float2(0.f, 0.f);
    float c0 = 0.f, c1 = 0.f, hv0 = 0.f, hv1 = 0.f;

    // prologue Xg load for step 0 (xgemm kernel finished before we started)
    const float* xr = g_xg + (size_t)gb * GATE + gc;
    float2 xi = *reinterpret_cast<const float2*>(xr + 0 * 512);
    float2 xf = *reinterpret_cast<const float2*>(xr + 1 * 512);
    float2 xg = *reinterpret_cast<const float2*>(xr + 2 * 512);
    float2 xo = *reinterpret_cast<const float2*>(xr + 3 * 512);

    grid_barrier();

    int p = 0;
    for (int s = 0; s < SEQ; s++) {
        const float* hsrc = g_h[p];

        float acc[4][4][4];
#pragma unroll
        for (int mt = 0; mt < 4; mt++)
#pragma unroll
            for (int nt = 0; nt < 4; nt++)
#pragma unroll
                for (int i = 0; i < 4; i++) acc[mt][nt][i] = 0.f;

        // ---- h @ W_hh^T partial over this warp's k slice, 3-deep pipelined ----
        const float* hb[4];
#pragma unroll
        for (int nt = 0; nt < 4; nt++)
            hb[nt] = hsrc + (size_t)(nb0 + nt * 8 + g) * HID + ks + tig;

        float fb[3][4][2];
#pragma unroll
        for (int st = 0; st < 2; st++)
#pragma unroll
            for (int nt = 0; nt < 4; nt++) {
                fb[st][nt][0] = __ldcg(hb[nt] + st * 8);
                fb[st][nt][1] = __ldcg(hb[nt] + st * 8 + 4);
            }
#pragma unroll
        for (int kt = 0; kt < 8; kt++) {
            const int cur = kt % 3;
            if (kt < 6) {
                const int slot = (kt + 2) % 3;
#pragma unroll
                for (int nt = 0; nt < 4; nt++) {
                    fb[slot][nt][0] = __ldcg(hb[nt] + (kt + 2) * 8);
                    fb[slot][nt][1] = __ldcg(hb[nt] + (kt + 2) * 8 + 4);
                }
            }
            uint32_t bb[4][2];
#pragma unroll
            for (int nt = 0; nt < 4; nt++) {
                bb[nt][0] = f2tf32(fb[cur][nt][0]);
                bb[nt][1] = f2tf32(fb[cur][nt][1]);
            }
#pragma unroll
            for (int mt = 0; mt < 4; mt++)
#pragma unroll
                for (int nt = 0; nt < 4; nt++)
                    mma_tf32(acc[mt][nt], wfr[mt][kt], bb[nt]);
        }

        // ---- store k-partials to smem ----
        float* pw = part + warp * (64 * 34);
#pragma unroll
        for (int mt = 0; mt < 4; mt++)
#pragma unroll
            for (int nt = 0; nt < 4; nt++) {
                const int row = mt * 16 + g, col = nt * 8 + 2 * tig;
                *reinterpret_cast<float2*>(pw + row * 34 + col) =
                    make_float2(acc[mt][nt][0], acc[mt][nt][1]);
                *reinterpret_cast<float2*>(pw + (row + 8) * 34 + col) =
                    make_float2(acc[mt][nt][2], acc[mt][nt][3]);
            }
        __syncthreads();

        // ---- reduce 8 partials + activations + state update ----
        float sg[4][2];
#pragma unroll
        for (int gt = 0; gt < 4; gt++)
#pragma unroll
            for (int j = 0; j < 2; j++) {
                const int base = (gt * 16 + r + j) * 34 + cb;
                float v = part[base];
#pragma unroll
                for (int w = 1; w < 8; w++) v += part[w * (64 * 34) + base];
                sg[gt][j] = v;
            }

        const float i0 = sigf(xi.x + sg[0][0]);
        const float i1 = sigf(xi.y + sg[0][1]);
        const float f0 = sigf(xf.x + sg[1][0]);
        const float f1 = sigf(xf.y + sg[1][1]);
        const float g0 = tanhfast(xg.x + sg[2][0]);
        const float g1 = tanhfast(xg.y + sg[2][1]);
        const float o0 = sigf(xo.x + sg[3][0]);
        const float o1 = sigf(xo.y + sg[3][1]);

        c0 = f0 * c0 + i0 * g0;
        c1 = f1 * c1 + i1 * g1;
        hv0 = o0 * tanhfast(c0);
        hv1 = o1 * tanhfast(c1);

        const float2 hvv = make_float2(hv0, hv1);
        *reinterpret_cast<float2*>(&g_h[p ^ 1][gb * HID + gc]) = hvv;
        *reinterpret_cast<float2*>(out + ((size_t)s * BATCH + gb) * HID + gc) = hvv;

        // prefetch Xg for s+1 — issued before the barrier so DRAM latency
        // overlaps the spin wait
        if (s + 1 < SEQ) {
            const float* xr2 = g_xg + ((size_t)(s + 1) * BATCH + gb) * GATE + gc;
            xi = *reinterpret_cast<const float2*>(xr2 + 0 * 512);
            xf = *reinterpret_cast<const float2*>(xr2 + 1 * 512);
            xg = *reinterpret_cast<const float2*>(xr2 + 2 * 512);
            xo = *reinterpret_cast<const float2*>(xr2 + 3 * 512);
        }

        grid_barrier();
        p ^= 1;
    }

    // final h, c
    float* hf = out + (size_t)SEQ * BATCH * HID;
    float* cf = hf + (size_t)BATCH * HID;
    *reinterpret_cast<float2*>(hf + gb * HID + gc) = make_float2(hv0, hv1);
    *reinterpret_cast<float2*>(cf + gb * HID + gc) = make_float2(c0, c1);
}

// =============================================================================
extern "C" void kernel_launch(void* const* d_in, const int* in_sizes, int n_in,
                              void* d_out, int out_size) {
    const float* x   = (const float*)d_in[0];
    const float* Wih = (const float*)d_in[1];
    const float* Whh = (const float*)d_in[2];
    const float* bih = (const float*)d_in[3];
    const float* bhh = (const float*)d_in[4];
    float* out = (float*)d_out;

    dim3 grid1(16, 1024);
    lstm_xgemm<<<grid1, 256>>>(x, Wih, bih, bhh);

    const int smem2 = 8 * 64 * 34 * (int)sizeof(float);  // 69632
    cudaFuncSetAttribute(lstm_rec, cudaFuncAttributeMaxDynamicSharedMemorySize, smem2);
    lstm_rec<<<NBLK, 256, smem2>>>(Whh, out);
}

// round 6
// speedup vs baseline: 1.1379x; 1.1275x over previous
#include <cuda_runtime.h>
#include <cuda_fp16.h>
#include <cstdint>

#define SEQ   2048
#define BATCH 64
#define DIM   512
#define HID   512
#define GATE  2048   // 4*HID
#define NBLK  64

// ---------------- device scratch (static globals are allowed) ---------------
__device__ float  g_xg[(size_t)SEQ * BATCH * GATE];  // precomputed input gates [S*B][4H]
__device__ __half g_hh[2][BATCH * HID];              // double-buffered hidden state (fp16)

struct alignas(128) PadU { unsigned v; unsigned pad[31]; };
__device__ PadU g_sub[2][4];   // per-group 4 sub-counters (8 CTAs each)
__device__ PadU g_root[2];     // per-group root counter
__device__ PadU g_gen[2];      // per-group generation

// ---------------- helpers ----------------------------------------------------
__device__ __forceinline__ uint32_t pack_h2(float a, float b) {
    __half2 h = __floats2half2_rn(a, b);
    return *reinterpret_cast<uint32_t*>(&h);
}
__device__ __forceinline__ uint32_t ldcg_u32(const void* p) {
    uint32_t v;
    asm volatile("ld.global.cg.b32 %0, [%1];" : "=r"(v) : "l"(p));
    return v;
}
__device__ __forceinline__ void mma_f16(float* c, const uint32_t* a, const uint32_t* b) {
    asm volatile(
        "mma.sync.aligned.m16n8k16.row.col.f32.f16.f16.f32 "
        "{%0,%1,%2,%3}, {%4,%5,%6,%7}, {%8,%9}, {%0,%1,%2,%3};"
        : "+f"(c[0]), "+f"(c[1]), "+f"(c[2]), "+f"(c[3])
        : "r"(a[0]), "r"(a[1]), "r"(a[2]), "r"(a[3]), "r"(b[0]), "r"(b[1]));
}
__device__ __forceinline__ float sigf(float x) { return 1.0f / (1.0f + __expf(-x)); }
__device__ __forceinline__ float tanhfast(float x) { return 2.0f / (1.0f + __expf(-2.0f * x)) - 1.0f; }

// =============================================================================
// Phase 1: Xg[m, n] = x[m, :] . W_ih[n, :] + b_ih[n] + b_hh[n]   (fp16 mma)
// M = 131072, N = 2048, K = 512. Block 128x128 (256 thr), warp 64x32.
// =============================================================================
__global__ __launch_bounds__(256) void lstm_xgemm(
    const float* __restrict__ x, const float* __restrict__ Wih,
    const float* __restrict__ bih, const float* __restrict__ bhh)
{
    __shared__ __half As[128 * 40];
    __shared__ __half Bs[128 * 40];
    __shared__ float  bsum[128];

    const int t = threadIdx.x;
    const int warp = t >> 5, lane = t & 31;
    const int wm = warp & 1;    // m offset (0/1)*64
    const int wn = warp >> 1;   // n offset (0..3)*32
    const int g = lane >> 2, tig = lane & 3;
    const int m0 = blockIdx.y * 128;
    const int n0 = blockIdx.x * 128;

    if (t < 128) bsum[t] = bih[n0 + t] + bhh[n0 + t];

    float acc[4][4][4];
#pragma unroll
    for (int mt = 0; mt < 4; mt++)
#pragma unroll
        for (int nt = 0; nt < 4; nt++)
#pragma unroll
            for (int i = 0; i < 4; i++) acc[mt][nt][i] = 0.f;

    for (int kc = 0; kc < 512; kc += 32) {
        __syncthreads();
        // A tile: 128 rows x 32 cols (fp32 -> fp16)
#pragma unroll
        for (int i = 0; i < 4; i++) {
            int f = t + i * 256;
            int row = f >> 3, q = (f & 7) * 4;
            float4 v = *reinterpret_cast<const float4*>(x + (size_t)(m0 + row) * 512 + kc + q);
            __half2* d = reinterpret_cast<__half2*>(As + row * 40 + q);
            d[0] = __floats2half2_rn(v.x, v.y);
            d[1] = __floats2half2_rn(v.z, v.w);
        }
        // B tile: 128 rows x 32 cols
#pragma unroll
        for (int i = 0; i < 4; i++) {
            int f = t + i * 256;
            int row = f >> 3, q = (f & 7) * 4;
            float4 v = *reinterpret_cast<const float4*>(Wih + (size_t)(n0 + row) * 512 + kc + q);
            __half2* d = reinterpret_cast<__half2*>(Bs + row * 40 + q);
            d[0] = __floats2half2_rn(v.x, v.y);
            d[1] = __floats2half2_rn(v.z, v.w);
        }
        __syncthreads();

#pragma unroll
        for (int kt = 0; kt < 2; kt++) {
            const int k0 = kt * 16;
            uint32_t a[4][4], b[4][2];
#pragma unroll
            for (int mt = 0; mt < 4; mt++) {
                const int r = wm * 64 + mt * 16;
                a[mt][0] = *reinterpret_cast<const uint32_t*>(As + (r + g)     * 40 + k0 + 2 * tig);
                a[mt][1] = *reinterpret_cast<const uint32_t*>(As + (r + g + 8) * 40 + k0 + 2 * tig);
                a[mt][2] = *reinterpret_cast<const uint32_t*>(As + (r + g)     * 40 + k0 + 2 * tig + 8);
                a[mt][3] = *reinterpret_cast<const uint32_t*>(As + (r + g + 8) * 40 + k0 + 2 * tig + 8);
            }
#pragma unroll
            for (int nt = 0; nt < 4; nt++) {
                const int rn = wn * 32 + nt * 8;
                b[nt][0] = *reinterpret_cast<const uint32_t*>(Bs + (rn + g) * 40 + k0 + 2 * tig);
                b[nt][1] = *reinterpret_cast<const uint32_t*>(Bs + (rn + g) * 40 + k0 + 2 * tig + 8);
            }
#pragma unroll
            for (int mt = 0; mt < 4; mt++)
#pragma unroll
                for (int nt = 0; nt < 4; nt++)
                    mma_f16(acc[mt][nt], a[mt], b[nt]);
        }
    }

#pragma unroll
    for (int mt = 0; mt < 4; mt++) {
        const int r0 = m0 + wm * 64 + mt * 16 + g;
#pragma unroll
        for (int nt = 0; nt < 4; nt++) {
            const int cl = wn * 32 + nt * 8 + 2 * tig;
            const float b0 = bsum[cl], b1 = bsum[cl + 1];
            float2 v0 = make_float2(acc[mt][nt][0] + b0, acc[mt][nt][1] + b1);
            float2 v1 = make_float2(acc[mt][nt][2] + b0, acc[mt][nt][3] + b1);
            *reinterpret_cast<float2*>(g_xg + (size_t)r0 * GATE + n0 + cl)       = v0;
            *reinterpret_cast<float2*>(g_xg + (size_t)(r0 + 8) * GATE + n0 + cl) = v1;
        }
    }
}

// =============================================================================
// Phase 2: persistent recurrence. Two INDEPENDENT groups of 32 CTAs (one per
// batch half; each CTA only reads its own batch-group's h rows). 2-level
// arrive (4 sub-counters of 8 + root) + release/acquire gen, no fences.
// =============================================================================
__device__ __forceinline__ void group_barrier(int bg, int cg) {
    __syncthreads();
    if (threadIdx.x == 0) {
        unsigned* subp  = &g_sub[bg][cg >> 3].v;
        unsigned* rootp = &g_root[bg].v;
        unsigned* genp  = &g_gen[bg].v;
        unsigned gv;
        asm volatile("ld.acquire.gpu.global.u32 %0, [%1];" : "=r"(gv) : "l"(genp) : "memory");
        unsigned so;
        asm volatile("atom.acq_rel.gpu.global.add.u32 %0, [%1], %2;"
                     : "=r"(so) : "l"(subp), "r"(1u) : "memory");
        bool done = false;
        if (so == 7u) {
            unsigned ro;
            asm volatile("atom.acq_rel.gpu.global.add.u32 %0, [%1], %2;"
                         : "=r"(ro) : "l"(rootp), "r"(1u) : "memory");
            if (ro == 3u) {
#pragma unroll
                for (int i = 0; i < 4; i++)
                    asm volatile("st.relaxed.gpu.global.u32 [%0], %1;"
                                 :: "l"(&g_sub[bg][i].v), "r"(0u) : "memory");
                asm volatile("st.relaxed.gpu.global.u32 [%0], %1;" :: "l"(rootp), "r"(0u) : "memory");
                asm volatile("st.release.gpu.global.u32 [%0], %1;" :: "l"(genp), "r"(gv + 1u) : "memory");
                done = true;
            }
        }
        if (!done) {
            unsigned cur;
            while (true) {
                asm volatile("ld.acquire.gpu.global.u32 %0, [%1];" : "=r"(cur) : "l"(genp) : "memory");
                if (cur != gv) break;
                __nanosleep(32);
            }
        }
    }
    __syncthreads();
}

__global__ __launch_bounds__(256) void lstm_rec(const float* __restrict__ Whh,
                                                float* __restrict__ out)
{
    extern __shared__ float part[];   // [8 warps][64 rows][34] floats = 69632 B
    const int t = threadIdx.x, warp = t >> 5, lane = t & 31;
    const int g = lane >> 2, tig = lane & 3;
    const int bg = blockIdx.x & 1;
    const int cg = blockIdx.x >> 1;
    const int nb0 = bg * 32;          // batch base
    const int hc0 = cg * 16;          // h-column base (gate-row base within each gate)
    const int ks = warp * 64;         // this warp's k-slice

    // ---- resident W_hh fragments (fp16 m16n8k16 A-frags), 64 regs/thread ----
    uint32_t wfr[4][4][4];            // [gate mt][kt (K16)][reg]
#pragma unroll
    for (int mt = 0; mt < 4; mt++) {
        const float* w0 = Whh + (size_t)(mt * 512 + hc0 + g) * 512;
        const float* w8 = Whh + (size_t)(mt * 512 + hc0 + g + 8) * 512;
#pragma unroll
        for (int kt = 0; kt < 4; kt++) {
            const int k = ks + kt * 16 + 2 * tig;
            wfr[mt][kt][0] = pack_h2(w0[k],     w0[k + 1]);
            wfr[mt][kt][1] = pack_h2(w8[k],     w8[k + 1]);
            wfr[mt][kt][2] = pack_h2(w0[k + 8], w0[k + 9]);
            wfr[mt][kt][3] = pack_h2(w8[k + 8], w8[k + 9]);
        }
    }

    // output mapping: this thread owns (h-cols gc, gc+1) x batch gb
    const int r  = 2 * (t & 7);       // local col pair base, 0..14
    const int cb = t >> 3;            // local batch, 0..31
    const int gb = nb0 + cb;
    const int gc = hc0 + r;

    // init h0 = 0, c0 = 0
    *reinterpret_cast<uint32_t*>(&g_hh[0][gb * HID + gc]) = 0u;
    float c0 = 0.f, c1 = 0.f, hv0 = 0.f, hv1 = 0.f;

    // prologue Xg load for step 0
    const float* xr = g_xg + (size_t)gb * GATE + gc;
    float2 xi = *reinterpret_cast<const float2*>(xr + 0 * 512);
    float2 xf = *reinterpret_cast<const float2*>(xr + 1 * 512);
    float2 xg = *reinterpret_cast<const float2*>(xr + 2 * 512);
    float2 xo = *reinterpret_cast<const float2*>(xr + 3 * 512);

    group_barrier(bg, cg);

    int p = 0;
    for (int s = 0; s < SEQ; s++) {
        const __half* hsrc = g_hh[p];

        float acc[4][4][4];
#pragma unroll
        for (int mt = 0; mt < 4; mt++)
#pragma unroll
            for (int nt = 0; nt < 4; nt++)
#pragma unroll
                for (int i = 0; i < 4; i++) acc[mt][nt][i] = 0.f;

        // ---- h @ W_hh^T partial over this warp's K=64 slice, 2-stage pipe ----
        uint32_t bb[2][4][2];
#pragma unroll
        for (int nt = 0; nt < 4; nt++) {
            const __half* hp = hsrc + (size_t)(nb0 + nt * 8 + g) * HID + ks + 2 * tig;
            bb[0][nt][0] = ldcg_u32(hp);
            bb[0][nt][1] = ldcg_u32(hp + 8);
        }
#pragma unroll
        for (int kt = 0; kt < 4; kt++) {
            const int cur = kt & 1;
            if (kt < 3) {
#pragma unroll
                for (int nt = 0; nt < 4; nt++) {
                    const __half* hp = hsrc + (size_t)(nb0 + nt * 8 + g) * HID
                                     + ks + (kt + 1) * 16 + 2 * tig;
                    bb[cur ^ 1][nt][0] = ldcg_u32(hp);
                    bb[cur ^ 1][nt][1] = ldcg_u32(hp + 8);
                }
            }
#pragma unroll
            for (int mt = 0; mt < 4; mt++)
#pragma unroll
                for (int nt = 0; nt < 4; nt++)
                    mma_f16(acc[mt][nt], wfr[mt][kt], bb[cur][nt]);
        }

        // ---- store k-partials to smem ----
        float* pw = part + warp * (64 * 34);
#pragma unroll
        for (int mt = 0; mt < 4; mt++)
#pragma unroll
            for (int nt = 0; nt < 4; nt++) {
                const int row = mt * 16 + g, col = nt * 8 + 2 * tig;
                *reinterpret_cast<float2*>(pw + row * 34 + col) =
                    make_float2(acc[mt][nt][0], acc[mt][nt][1]);
                *reinterpret_cast<float2*>(pw + (row + 8) * 34 + col) =
                    make_float2(acc[mt][nt][2], acc[mt][nt][3]);
            }
        __syncthreads();

        // ---- reduce 8 partials + activations + state update ----
        float sg[4][2];
#pragma unroll
        for (int gt = 0; gt < 4; gt++)
#pragma unroll
            for (int j = 0; j < 2; j++) {
                const int base = (gt * 16 + r + j) * 34 + cb;
                float v = part[base];
#pragma unroll
                for (int w = 1; w < 8; w++) v += part[w * (64 * 34) + base];
                sg[gt][j] = v;
            }

        const float i0 = sigf(xi.x + sg[0][0]);
        const float i1 = sigf(xi.y + sg[0][1]);
        const float f0 = sigf(xf.x + sg[1][0]);
        const float f1 = sigf(xf.y + sg[1][1]);
        const float g0 = tanhfast(xg.x + sg[2][0]);
        const float g1 = tanhfast(xg.y + sg[2][1]);
        const float o0 = sigf(xo.x + sg[3][0]);
        const float o1 = sigf(xo.y + sg[3][1]);

        c0 = f0 * c0 + i0 * g0;
        c1 = f1 * c1 + i1 * g1;
        hv0 = o0 * tanhfast(c0);
        hv1 = o1 * tanhfast(c1);

        // publish h (fp16) + output (fp32)
        *reinterpret_cast<uint32_t*>(&g_hh[p ^ 1][gb * HID + gc]) = pack_h2(hv0, hv1);
        *reinterpret_cast<float2*>(out + ((size_t)s * BATCH + gb) * HID + gc) = make_float2(hv0, hv1);

        // prefetch Xg for s+1 (latency overlaps barrier spin)
        if (s + 1 < SEQ) {
            const float* xr2 = g_xg + ((size_t)(s + 1) * BATCH + gb) * GATE + gc;
            xi = *reinterpret_cast<const float2*>(xr2 + 0 * 512);
            xf = *reinterpret_cast<const float2*>(xr2 + 1 * 512);
            xg = *reinterpret_cast<const float2*>(xr2 + 2 * 512);
            xo = *reinterpret_cast<const float2*>(xr2 + 3 * 512);
        }

        group_barrier(bg, cg);
        p ^= 1;
    }

    // final h, c
    float* hf = out + (size_t)SEQ * BATCH * HID;
    float* cf = hf + (size_t)BATCH * HID;
    *reinterpret_cast<float2*>(hf + gb * HID + gc) = make_float2(hv0, hv1);
    *reinterpret_cast<float2*>(cf + gb * HID + gc) = make_float2(c0, c1);
}

// =============================================================================
extern "C" void kernel_launch(void* const* d_in, const int* in_sizes, int n_in,
                              void* d_out, int out_size) {
    const float* x   = (const float*)d_in[0];
    const float* Wih = (const float*)d_in[1];
    const float* Whh = (const float*)d_in[2];
    const float* bih = (const float*)d_in[3];
    const float* bhh = (const float*)d_in[4];
    float* out = (float*)d_out;

    dim3 grid1(16, 1024);
    lstm_xgemm<<<grid1, 256>>>(x, Wih, bih, bhh);

    const int smem2 = 8 * 64 * 34 * (int)sizeof(float);  // 69632
    cudaFuncSetAttribute(lstm_rec, cudaFuncAttributeMaxDynamicSharedMemorySize, smem2);
    lstm_rec<<<NBLK, 256, smem2>>>(Whh, out);
}